// round 9
// baseline (speedup 1.0000x reference)
#include <cuda_runtime.h>
#include <math.h>

#define N_DIM    64
#define B_ROWS   1024
#define QCH      32
#define NBLK_K2  (N_DIM * 16)      // 1024
#define NGRP     64                // knn row-groups of 16
#define NQ       8                 // j-eighths (128 js each)
#define NBLK_KNN (NGRP * NQ)       // 512
#define TS       3.5f              // truncation radius, h-units
#define K2C      (-0.72134752f)    // -0.5*log2(e)
#define NMOM     13                // Hermite terms 0..12

// Scratch (device globals — no allocation allowed)
__device__ float g_logrho[B_ROWS];
__device__ float g_cols[N_DIM * B_ROWS];   // sorted columns, scaled by 1/h
__device__ float g_invh[N_DIM];
__device__ float g_partials[N_DIM * QCH];
__device__ float g_t6[NGRP][NQ][16][6];
__device__ int   g_qc[NGRP];
__device__ int   g_done;

__device__ __forceinline__ float ex2(float x) {
    float r;
    asm("ex2.approx.ftz.f32 %0, %1;" : "=f"(r) : "f"(x));
    return r;
}

// ---------------------------------------------------------------------------
// Kernel 1: knn (blocks 0..511) + prep (blocks 512..575), 128 threads.
// knn block: 16 rows (4/warp, 4 warps), 128 js (1 tile); fused shuffle norms.
// ---------------------------------------------------------------------------
struct KnnS {
    float tile[128][68];
    float xq[16][64];
    float jn[128];
    float qn[16];
    int   merge;
};
struct PrepS {
    float u[B_ROWS];
    float red[128];
    float scale;
};

__global__ __launch_bounds__(128)
void k1(const float* __restrict__ act, const int* __restrict__ kp) {
    __shared__ __align__(16) char sm[sizeof(KnnS) > sizeof(PrepS) ? sizeof(KnnS) : sizeof(PrepS)];
    const int tid = threadIdx.x;
    const int bx  = blockIdx.x;

    if (bx == 0 && tid == 0) g_done = 0;

    if (bx < NBLK_KNN) {
        KnnS* S = (KnnS*)sm;
        const int g = bx >> 3, q = bx & 7;
        const int row0 = g * 16, jbase = q * 128;
        const int lane = tid & 31, w = tid >> 5;

        // 16 query rows + norms (half-warp shuffle reduce)
        {
            const float4* qsrc = (const float4*)(act + row0 * N_DIM);
            #pragma unroll
            for (int t = 0; t < 2; t++) {
                int fi = tid + t * 128;
                float4 v = qsrc[fi];
                ((float4*)S->xq)[fi] = v;
                float s = v.x * v.x + v.y * v.y + v.z * v.z + v.w * v.w;
                s += __shfl_down_sync(0xffffffffu, s, 8, 16);
                s += __shfl_down_sync(0xffffffffu, s, 4, 16);
                s += __shfl_down_sync(0xffffffffu, s, 2, 16);
                s += __shfl_down_sync(0xffffffffu, s, 1, 16);
                if ((lane & 15) == 0) S->qn[fi >> 4] = s;
            }
        }
        // j tile + norms fused
        {
            const float4* gsrc = (const float4*)(act + jbase * N_DIM);
            #pragma unroll
            for (int it = 0; it < 16; it++) {
                int fi = tid + it * 128;
                float4 v = gsrc[fi];
                *(float4*)&S->tile[fi >> 4][(fi & 15) * 4] = v;
                float s = v.x * v.x + v.y * v.y + v.z * v.z + v.w * v.w;
                s += __shfl_down_sync(0xffffffffu, s, 8, 16);
                s += __shfl_down_sync(0xffffffffu, s, 4, 16);
                s += __shfl_down_sync(0xffffffffu, s, 2, 16);
                s += __shfl_down_sync(0xffffffffu, s, 1, 16);
                if ((lane & 15) == 0) S->jn[fi >> 4] = s;
            }
        }
        __syncthreads();

        float m[4][6];
        #pragma unroll
        for (int r = 0; r < 4; r++)
            #pragma unroll
            for (int i = 0; i < 6; i++) m[r][i] = 3.4e38f;

        float acc[4][4];
        #pragma unroll
        for (int r = 0; r < 4; r++)
            #pragma unroll
            for (int s = 0; s < 4; s++) acc[r][s] = 0.f;

        #pragma unroll
        for (int c = 0; c < 8; c++) {
            float4 qr[4][2];
            #pragma unroll
            for (int r = 0; r < 4; r++) {
                qr[r][0] = *(const float4*)&S->xq[4 * w + r][c * 8];
                qr[r][1] = *(const float4*)&S->xq[4 * w + r][c * 8 + 4];
            }
            #pragma unroll
            for (int s = 0; s < 4; s++) {
                const int j = lane + 32 * s;
                const float4 b0 = *(const float4*)&S->tile[j][c * 8];
                const float4 b1 = *(const float4*)&S->tile[j][c * 8 + 4];
                #pragma unroll
                for (int r = 0; r < 4; r++) {
                    float a = acc[r][s];
                    a = fmaf(qr[r][0].x, b0.x, a);
                    a = fmaf(qr[r][0].y, b0.y, a);
                    a = fmaf(qr[r][0].z, b0.z, a);
                    a = fmaf(qr[r][0].w, b0.w, a);
                    a = fmaf(qr[r][1].x, b1.x, a);
                    a = fmaf(qr[r][1].y, b1.y, a);
                    a = fmaf(qr[r][1].z, b1.z, a);
                    a = fmaf(qr[r][1].w, b1.w, a);
                    acc[r][s] = a;
                }
            }
        }
        #pragma unroll
        for (int s = 0; s < 4; s++) {
            const float nj = S->jn[lane + 32 * s];
            #pragma unroll
            for (int r = 0; r < 4; r++) {
                float v = fmaf(acc[r][s], -2.f, nj);
                if (v < m[r][5]) {
                    m[r][5] = v;
                    #pragma unroll
                    for (int i = 5; i > 0; i--)
                        if (m[r][i] < m[r][i - 1]) {
                            float tm = m[r][i]; m[r][i] = m[r][i - 1]; m[r][i - 1] = tm;
                        }
                }
            }
        }

        #pragma unroll
        for (int r = 0; r < 4; r++) {
            float l0 = m[r][0], l1 = m[r][1], l2 = m[r][2];
            float l3 = m[r][3], l4 = m[r][4], l5 = m[r][5];
            float keep = 3.4e38f;
            #pragma unroll
            for (int i = 0; i < 6; i++) {
                float mv = l0;
                #pragma unroll
                for (int off = 16; off; off >>= 1)
                    mv = fminf(mv, __shfl_xor_sync(0xffffffffu, mv, off));
                if (lane == i) keep = mv;
                unsigned msk = __ballot_sync(0xffffffffu, l0 == mv);
                if (lane == (__ffs(msk) - 1)) {
                    l0 = l1; l1 = l2; l2 = l3; l3 = l4; l4 = l5; l5 = 3.4e38f;
                }
            }
            if (lane < 6)
                g_t6[g][q][4 * w + r][lane] = keep + S->qn[4 * w + r];
        }
        __syncthreads();
        if (tid == 0) {
            __threadfence();
            int old = atomicAdd(&g_qc[g], 1);
            S->merge = (old == NQ - 1);
        }
        __syncthreads();
        if (S->merge) {
            __threadfence();
            if (tid < 16) {
                int kk = *kp; if (kk > 5) kk = 5;
                float best[6];
                #pragma unroll
                for (int i = 0; i < 6; i++) best[i] = 3.4e38f;
                #pragma unroll
                for (int qq = 0; qq < NQ; qq++) {
                    #pragma unroll
                    for (int i = 0; i < 6; i++) {
                        float v = g_t6[g][qq][tid][i];
                        if (v < best[5]) {
                            best[5] = v;
                            #pragma unroll
                            for (int j2 = 5; j2 > 0; j2--)
                                if (best[j2] < best[j2 - 1]) {
                                    float tm = best[j2]; best[j2] = best[j2 - 1]; best[j2 - 1] = tm;
                                }
                        }
                    }
                }
                g_logrho[row0 + tid] = logf(fmaxf(best[kk], 1e-12f));
            }
            if (tid == 0) g_qc[g] = 0;
        }
    } else {
        // ================= PREP (128 thr, 8 elems/thread) ================
        PrepS* P = (PrepS*)sm;
        const int col = bx - NBLK_KNN;
        float s1 = 0.f, s2 = 0.f;
        #pragma unroll
        for (int t = 0; t < 8; t++) {
            float v = act[(tid + 128 * t) * N_DIM + col];
            P->u[tid + 128 * t] = v;
            s1 += v;
            s2 += v * v;
        }
        P->red[tid] = s1; __syncthreads();
        for (int st = 64; st > 0; st >>= 1) {
            if (tid < st) P->red[tid] += P->red[tid + st];
            __syncthreads();
        }
        float tot1 = P->red[0]; __syncthreads();
        P->red[tid] = s2; __syncthreads();
        for (int st = 64; st > 0; st >>= 1) {
            if (tid < st) P->red[tid] += P->red[tid + st];
            __syncthreads();
        }
        if (tid == 0) {
            const float Bf = (float)B_ROWS;
            float mean = tot1 / Bf;
            float var  = (P->red[0] - Bf * mean * mean) / (Bf - 1.0f);
            float stdv = sqrtf(fmaxf(var, 0.f));
            float h    = fmaxf(1.06f * stdv * 0.25f, 1e-4f);
            float ih   = 1.0f / h;
            g_invh[col] = ih;
            P->scale    = ih;
        }
        __syncthreads();
        const float sc = P->scale;
        #pragma unroll
        for (int t = 0; t < 8; t++)
            P->u[tid + 128 * t] *= sc;

        for (int kk2 = 2; kk2 <= B_ROWS; kk2 <<= 1) {
            for (int jj = kk2 >> 1; jj > 0; jj >>= 1) {
                __syncthreads();
                #pragma unroll
                for (int t = 0; t < 8; t++) {
                    int i = tid + 128 * t;
                    int ixj = i ^ jj;
                    if (ixj > i) {
                        bool up = ((i & kk2) == 0);
                        float a = P->u[i], b = P->u[ixj];
                        if ((a > b) == up) { P->u[i] = b; P->u[ixj] = a; }
                    }
                }
            }
        }
        __syncthreads();
        #pragma unroll
        for (int t = 0; t < 8; t++)
            g_cols[col * B_ROWS + tid + 128 * t] = P->u[tid + 128 * t];
    }
}

// ---------------------------------------------------------------------------
// Kernel 2: KDE via Hermite moments (13 terms), reflections direct.
// grid=(64,16), block=256; halves handle chunks cp and 31-cp.
// ---------------------------------------------------------------------------
__global__ __launch_bounds__(256)
void k2(const int* __restrict__ kp, float* __restrict__ out) {
    __shared__ __align__(16) float u[B_ROWS];
    __shared__ float refl[2][32][5];
    __shared__ float mom[2][4][NMOM];
    __shared__ int   bnd[2][4];
    __shared__ double dred[256];
    __shared__ int   sdone;

    const int tid  = threadIdx.x;
    const int lane = tid & 31;
    const int w    = tid >> 5;
    const int half = w >> 2;
    const int wl   = w & 3;
    const int col  = blockIdx.x;
    const int cp   = blockIdx.y;
    const int chunk = half ? (31 - cp) : cp;

    ((float4*)u)[tid] = ((const float4*)(g_cols + col * B_ROWS))[tid];
    __syncthreads();

    const float ih = g_invh[col];
    const int   q0 = chunk * 32;
    const float x  = u[q0 + lane];
    const float c2 = 2.0f * ih;
    const float cen = 0.5f * (u[q0] + u[q0 + 31]);

    if (tid < 8) {
        int h2 = tid >> 2, i2 = tid & 3;
        int ch = h2 ? (31 - cp) : cp;
        float xmn = u[ch * 32], xmx = u[ch * 32 + 31];
        float tgt = (i2 == 0) ? xmn - TS : (i2 == 1) ? xmx + TS
                  : (i2 == 2) ? TS - xmn : c2 - TS - xmx;
        int pos = 0;
        #pragma unroll
        for (int step = 1024; step; step >>= 1) {
            int np = pos + step;
            if (np <= B_ROWS && u[np - 1] < tgt) pos = np;
        }
        bnd[h2][i2] = pos;
    }
    __syncthreads();
    const int a0 = bnd[half][0], b0 = bnd[half][1];
    const int bL = bnd[half][2], aR = bnd[half][3];

    // ---- Hermite moments over main window (all 128 threads of half) ----
    {
        constexpr float INV[NMOM] = {0.f, 1.f, 0.5f, 0.33333334f, 0.25f, 0.2f,
            0.16666667f, 0.14285715f, 0.125f, 0.11111111f, 0.1f, 0.09090909f,
            0.08333334f};
        float M[NMOM];
        #pragma unroll
        for (int n = 0; n < NMOM; n++) M[n] = 0.f;
        for (int j = a0 + (wl * 32 + lane); j < b0; j += 128) {
            float uj = u[j] - cen;
            float wgt = ex2(K2C * uj * uj);
            float bp = wgt, bc = wgt * uj;
            M[0] += bp;
            M[1] += bc;
            #pragma unroll
            for (int n = 1; n < NMOM - 1; n++) {
                float bn = fmaf(uj, bc, -bp) * INV[n + 1];
                M[n + 1] += bn;
                bp = bc; bc = bn;
            }
        }
        #pragma unroll
        for (int n = 0; n < NMOM; n++) {
            #pragma unroll
            for (int off = 16; off; off >>= 1)
                M[n] += __shfl_xor_sync(0xffffffffu, M[n], off);
        }
        if (lane == 0) {
            #pragma unroll
            for (int n = 0; n < NMOM; n++) mom[half][wl][n] = M[n];
        }
    }

    // ---- reflections: direct, contiguous per-warp slices ----
    {
        float A0 = 0.f, A1 = 0.f;
        int l0 = (bL * wl) >> 2, l1 = (bL * (wl + 1)) >> 2;
        for (int j = l0; j < l1; j++) {
            float s = x + u[j];
            A1 += ex2(K2C * s * s);
        }
        const int rlen = B_ROWS - aR;
        const float xc = x - c2;
        int r0 = aR + ((rlen * wl) >> 2), r1 = aR + ((rlen * (wl + 1)) >> 2);
        for (int j = r0; j < r1; j++) {
            float s = xc + u[j];
            A0 += ex2(K2C * s * s);
        }
        refl[half][lane][wl] = A0 + A1;
    }
    __syncthreads();

    if (wl == 0) {
        float Mn[NMOM];
        #pragma unroll
        for (int n = 0; n < NMOM; n++)
            Mn[n] = (mom[half][0][n] + mom[half][1][n])
                  + (mom[half][2][n] + mom[half][3][n]);
        const float delta = x - cen;
        float f = Mn[NMOM - 1];
        #pragma unroll
        for (int n = NMOM - 2; n >= 0; n--)
            f = fmaf(f, delta, Mn[n]);
        f += (refl[half][lane][0] + refl[half][lane][1])
           + (refl[half][lane][2] + refl[half][lane][3]);

        const float Bf = (float)B_ROWS;
        const float scale = ih * (1.0f / (Bf * 2.5066282746310002f));
        float l = logf(f * scale + 1e-8f);
        #pragma unroll
        for (int off = 16; off; off >>= 1)
            l += __shfl_xor_sync(0xffffffffu, l, off);
        if (lane == 0)
            g_partials[col * QCH + chunk] = l;
    }
    __syncthreads();

    if (tid == 0) {
        __threadfence();
        unsigned p = atomicAdd(&g_done, 1);
        sdone = (p == NBLK_K2 - 1);
    }
    __syncthreads();
    if (!sdone) return;
    __threadfence();

    if (tid < N_DIM) {
        float t = 0.f;
        #pragma unroll
        for (int c = 0; c < QCH; c++)
            t += g_partials[tid * QCH + c];
        out[1 + tid] = -t / (float)B_ROWS;
    }
    double s = 0.0;
    for (int i = tid; i < B_ROWS; i += 256) s += (double)g_logrho[i];
    dred[tid] = s; __syncthreads();
    for (int st = 128; st > 0; st >>= 1) {
        if (tid < st) dred[tid] += dred[tid + st];
        __syncthreads();
    }
    if (tid == 0) {
        const int k = *kp;
        const double EULER    = 0.5772156649015328606;
        const double DG_B     = 6.9309834448765934;     // psi(1024)
        const double LGAMMA33 = 81.55795945611503558;   // lgamma(64/2+1)
        const double LOG_PI   = 1.1447298858494001741;
        const double INV_LN2  = 1.4426950408889634074;
        double dg_k = -EULER;
        for (int i = 1; i < k; i++) dg_k += 1.0 / (double)i;
        double log_c_d = 0.5 * (double)N_DIM * LOG_PI - LGAMMA33;
        double mean_lr = dred[0] / (double)B_ROWS;
        double h_nats = -dg_k + DG_B + log_c_d + (double)N_DIM * 0.5 * mean_lr;
        out[0] = (float)(h_nats * INV_LN2);
    }
}

// ---------------------------------------------------------------------------
extern "C" void kernel_launch(void* const* d_in, const int* in_sizes, int n_in,
                              void* d_out, int out_size) {
    const float* act = (const float*)d_in[0];
    const int*   kp  = (const int*)d_in[1];
    float* out = (float*)d_out;
    (void)in_sizes; (void)n_in; (void)out_size;

    k1<<<NBLK_KNN + N_DIM, 128>>>(act, kp);
    dim3 g(N_DIM, 16);
    k2<<<g, 256>>>(kp, out);
}

// round 10
// speedup vs baseline: 1.2222x; 1.2222x over previous
#include <cuda_runtime.h>
#include <math.h>

#define N_DIM    64
#define B_ROWS   1024
#define QCH      32
#define NBLK_K2  (N_DIM * 16)      // 1024
#define NGRP     32                // knn row-groups of 32
#define NQ       8                 // j-eighths (128 js each)
#define NBLK_KNN (NGRP * NQ)       // 256
#define TS       3.5f              // truncation radius, h-units
#define K2C      (-0.72134752f)    // -0.5*log2(e)
#define NMOM     13                // Hermite terms 0..12

// Scratch (device globals — no allocation allowed)
__device__ float g_logrho[B_ROWS];
__device__ float g_cols[N_DIM * B_ROWS];   // sorted columns, scaled by 1/h
__device__ float g_invh[N_DIM];
__device__ float g_partials[N_DIM * QCH];
__device__ float g_t6[NGRP][NQ][32][6];
__device__ int   g_qc[NGRP];
__device__ int   g_done;

__device__ __forceinline__ float ex2(float x) {
    float r;
    asm("ex2.approx.ftz.f32 %0, %1;" : "=f"(r) : "f"(x));
    return r;
}

// ---------------------------------------------------------------------------
// Kernel 1: knn (blocks 0..255) + prep (blocks 256..319), 256 threads.
// knn block: 32 rows (4/warp, 8 warps), 128 js (1 tile); fused shuffle norms.
// ---------------------------------------------------------------------------
struct KnnS {
    float tile[128][68];   // stride 68: conflict-free LDS.128
    float xq[32][64];
    float jn[128];
    float qn[32];
    int   merge;
};
struct PrepS {
    float u[B_ROWS];
    float red[256];
    float scale;
};

__global__ __launch_bounds__(256)
void k1(const float* __restrict__ act, const int* __restrict__ kp) {
    __shared__ __align__(16) char sm[sizeof(KnnS) > sizeof(PrepS) ? sizeof(KnnS) : sizeof(PrepS)];
    const int tid = threadIdx.x;
    const int bx  = blockIdx.x;

    if (bx == 0 && tid == 0) g_done = 0;

    if (bx < NBLK_KNN) {
        KnnS* S = (KnnS*)sm;
        const int g = bx >> 3, q = bx & 7;
        const int row0 = g * 32, jbase = q * 128;
        const int lane = tid & 31, w = tid >> 5;

        // 32 query rows + norms (half-warp shuffle reduce)
        {
            const float4* qsrc = (const float4*)(act + row0 * N_DIM);
            #pragma unroll
            for (int t = 0; t < 2; t++) {
                int fi = tid + t * 256;
                float4 v = qsrc[fi];
                ((float4*)S->xq)[fi] = v;
                float s = v.x * v.x + v.y * v.y + v.z * v.z + v.w * v.w;
                s += __shfl_down_sync(0xffffffffu, s, 8, 16);
                s += __shfl_down_sync(0xffffffffu, s, 4, 16);
                s += __shfl_down_sync(0xffffffffu, s, 2, 16);
                s += __shfl_down_sync(0xffffffffu, s, 1, 16);
                if ((lane & 15) == 0) S->qn[fi >> 4] = s;
            }
        }
        // single j tile + norms fused
        {
            const float4* gsrc = (const float4*)(act + jbase * N_DIM);
            #pragma unroll
            for (int it = 0; it < 8; it++) {
                int fi = tid + it * 256;
                float4 v = gsrc[fi];
                *(float4*)&S->tile[fi >> 4][(fi & 15) * 4] = v;
                float s = v.x * v.x + v.y * v.y + v.z * v.z + v.w * v.w;
                s += __shfl_down_sync(0xffffffffu, s, 8, 16);
                s += __shfl_down_sync(0xffffffffu, s, 4, 16);
                s += __shfl_down_sync(0xffffffffu, s, 2, 16);
                s += __shfl_down_sync(0xffffffffu, s, 1, 16);
                if ((lane & 15) == 0) S->jn[fi >> 4] = s;
            }
        }
        __syncthreads();

        float m[4][6];
        #pragma unroll
        for (int r = 0; r < 4; r++)
            #pragma unroll
            for (int i = 0; i < 6; i++) m[r][i] = 3.4e38f;

        float acc[4][4];
        #pragma unroll
        for (int r = 0; r < 4; r++)
            #pragma unroll
            for (int s = 0; s < 4; s++) acc[r][s] = 0.f;

        #pragma unroll
        for (int c = 0; c < 8; c++) {      // 8-dim chunks
            float4 qr[4][2];
            #pragma unroll
            for (int r = 0; r < 4; r++) {
                qr[r][0] = *(const float4*)&S->xq[4 * w + r][c * 8];
                qr[r][1] = *(const float4*)&S->xq[4 * w + r][c * 8 + 4];
            }
            #pragma unroll
            for (int s = 0; s < 4; s++) {
                const int j = lane + 32 * s;
                const float4 b0 = *(const float4*)&S->tile[j][c * 8];
                const float4 b1 = *(const float4*)&S->tile[j][c * 8 + 4];
                #pragma unroll
                for (int r = 0; r < 4; r++) {
                    float a = acc[r][s];
                    a = fmaf(qr[r][0].x, b0.x, a);
                    a = fmaf(qr[r][0].y, b0.y, a);
                    a = fmaf(qr[r][0].z, b0.z, a);
                    a = fmaf(qr[r][0].w, b0.w, a);
                    a = fmaf(qr[r][1].x, b1.x, a);
                    a = fmaf(qr[r][1].y, b1.y, a);
                    a = fmaf(qr[r][1].z, b1.z, a);
                    a = fmaf(qr[r][1].w, b1.w, a);
                    acc[r][s] = a;
                }
            }
        }
        // candidates ranked by jn - 2*dot (qn constant per row)
        #pragma unroll
        for (int s = 0; s < 4; s++) {
            const float nj = S->jn[lane + 32 * s];
            #pragma unroll
            for (int r = 0; r < 4; r++) {
                float v = fmaf(acc[r][s], -2.f, nj);
                if (v < m[r][5]) {
                    m[r][5] = v;
                    #pragma unroll
                    for (int i = 5; i > 0; i--)
                        if (m[r][i] < m[r][i - 1]) {
                            float tm = m[r][i]; m[r][i] = m[r][i - 1]; m[r][i - 1] = tm;
                        }
                }
            }
        }

        // per-row: extract top-6 over 32 lanes, add qn, store
        #pragma unroll
        for (int r = 0; r < 4; r++) {
            float l0 = m[r][0], l1 = m[r][1], l2 = m[r][2];
            float l3 = m[r][3], l4 = m[r][4], l5 = m[r][5];
            float keep = 3.4e38f;
            #pragma unroll
            for (int i = 0; i < 6; i++) {
                float mv = l0;
                #pragma unroll
                for (int off = 16; off; off >>= 1)
                    mv = fminf(mv, __shfl_xor_sync(0xffffffffu, mv, off));
                if (lane == i) keep = mv;
                unsigned msk = __ballot_sync(0xffffffffu, l0 == mv);
                if (lane == (__ffs(msk) - 1)) {
                    l0 = l1; l1 = l2; l2 = l3; l3 = l4; l4 = l5; l5 = 3.4e38f;
                }
            }
            if (lane < 6)
                g_t6[g][q][4 * w + r][lane] = keep + S->qn[4 * w + r];
        }
        __syncthreads();
        if (tid == 0) {
            __threadfence();
            int old = atomicAdd(&g_qc[g], 1);
            S->merge = (old == NQ - 1);
        }
        __syncthreads();
        if (S->merge) {
            __threadfence();
            if (tid < 32) {
                int kk = *kp; if (kk > 5) kk = 5;
                float best[6];
                #pragma unroll
                for (int i = 0; i < 6; i++) best[i] = 3.4e38f;
                #pragma unroll
                for (int qq = 0; qq < NQ; qq++) {
                    #pragma unroll
                    for (int i = 0; i < 6; i++) {
                        float v = g_t6[g][qq][tid][i];
                        if (v < best[5]) {
                            best[5] = v;
                            #pragma unroll
                            for (int j2 = 5; j2 > 0; j2--)
                                if (best[j2] < best[j2 - 1]) {
                                    float tm = best[j2]; best[j2] = best[j2 - 1]; best[j2 - 1] = tm;
                                }
                        }
                    }
                }
                g_logrho[row0 + tid] = logf(fmaxf(best[kk], 1e-12f));
            }
            if (tid == 0) g_qc[g] = 0;   // reset for graph replay
        }
    } else {
        // ================= PREP (256 thr, 4 elems/thread) ================
        PrepS* P = (PrepS*)sm;
        const int col = bx - NBLK_KNN;
        float s1 = 0.f, s2 = 0.f;
        #pragma unroll
        for (int t = 0; t < 4; t++) {
            float v = act[(tid + 256 * t) * N_DIM + col];
            P->u[tid + 256 * t] = v;
            s1 += v;
            s2 += v * v;
        }
        P->red[tid] = s1; __syncthreads();
        for (int st = 128; st > 0; st >>= 1) {
            if (tid < st) P->red[tid] += P->red[tid + st];
            __syncthreads();
        }
        float tot1 = P->red[0]; __syncthreads();
        P->red[tid] = s2; __syncthreads();
        for (int st = 128; st > 0; st >>= 1) {
            if (tid < st) P->red[tid] += P->red[tid + st];
            __syncthreads();
        }
        if (tid == 0) {
            const float Bf = (float)B_ROWS;
            float mean = tot1 / Bf;
            float var  = (P->red[0] - Bf * mean * mean) / (Bf - 1.0f);
            float stdv = sqrtf(fmaxf(var, 0.f));
            float h    = fmaxf(1.06f * stdv * 0.25f, 1e-4f);
            float ih   = 1.0f / h;
            g_invh[col] = ih;
            P->scale    = ih;
        }
        __syncthreads();
        const float sc = P->scale;
        #pragma unroll
        for (int t = 0; t < 4; t++)
            P->u[tid + 256 * t] *= sc;

        for (int kk2 = 2; kk2 <= B_ROWS; kk2 <<= 1) {
            for (int jj = kk2 >> 1; jj > 0; jj >>= 1) {
                __syncthreads();
                #pragma unroll
                for (int t = 0; t < 4; t++) {
                    int i = tid + 256 * t;
                    int ixj = i ^ jj;
                    if (ixj > i) {
                        bool up = ((i & kk2) == 0);
                        float a = P->u[i], b = P->u[ixj];
                        if ((a > b) == up) { P->u[i] = b; P->u[ixj] = a; }
                    }
                }
            }
        }
        __syncthreads();
        #pragma unroll
        for (int t = 0; t < 4; t++)
            g_cols[col * B_ROWS + tid + 256 * t] = P->u[tid + 256 * t];
    }
}

// ---------------------------------------------------------------------------
// Kernel 2: KDE via Hermite moments (13 terms), reflections direct.
// grid=(64,16), block=256; halves handle chunks cp and 31-cp.
// ---------------------------------------------------------------------------
__global__ __launch_bounds__(256)
void k2(const int* __restrict__ kp, float* __restrict__ out) {
    __shared__ __align__(16) float u[B_ROWS];
    __shared__ float refl[2][32][5];
    __shared__ float mom[2][4][NMOM];
    __shared__ int   bnd[2][4];
    __shared__ double dred[256];
    __shared__ int   sdone;

    const int tid  = threadIdx.x;
    const int lane = tid & 31;
    const int w    = tid >> 5;
    const int half = w >> 2;
    const int wl   = w & 3;
    const int col  = blockIdx.x;
    const int cp   = blockIdx.y;
    const int chunk = half ? (31 - cp) : cp;

    ((float4*)u)[tid] = ((const float4*)(g_cols + col * B_ROWS))[tid];
    __syncthreads();

    const float ih = g_invh[col];
    const int   q0 = chunk * 32;
    const float x  = u[q0 + lane];
    const float c2 = 2.0f * ih;
    const float cen = 0.5f * (u[q0] + u[q0 + 31]);

    if (tid < 8) {
        int h2 = tid >> 2, i2 = tid & 3;
        int ch = h2 ? (31 - cp) : cp;
        float xmn = u[ch * 32], xmx = u[ch * 32 + 31];
        float tgt = (i2 == 0) ? xmn - TS : (i2 == 1) ? xmx + TS
                  : (i2 == 2) ? TS - xmn : c2 - TS - xmx;
        int pos = 0;
        #pragma unroll
        for (int step = 1024; step; step >>= 1) {
            int np = pos + step;
            if (np <= B_ROWS && u[np - 1] < tgt) pos = np;
        }
        bnd[h2][i2] = pos;
    }
    __syncthreads();
    const int a0 = bnd[half][0], b0 = bnd[half][1];
    const int bL = bnd[half][2], aR = bnd[half][3];

    // ---- Hermite moments over main window (128 threads of this half) ----
    {
        constexpr float INV[NMOM] = {0.f, 1.f, 0.5f, 0.33333334f, 0.25f, 0.2f,
            0.16666667f, 0.14285715f, 0.125f, 0.11111111f, 0.1f, 0.09090909f,
            0.08333334f};
        float M[NMOM];
        #pragma unroll
        for (int n = 0; n < NMOM; n++) M[n] = 0.f;
        for (int j = a0 + (wl * 32 + lane); j < b0; j += 128) {
            float uj = u[j] - cen;
            float wgt = ex2(K2C * uj * uj);
            float bp = wgt, bc = wgt * uj;
            M[0] += bp;
            M[1] += bc;
            #pragma unroll
            for (int n = 1; n < NMOM - 1; n++) {
                float bn = fmaf(uj, bc, -bp) * INV[n + 1];
                M[n + 1] += bn;
                bp = bc; bc = bn;
            }
        }
        #pragma unroll
        for (int n = 0; n < NMOM; n++) {
            #pragma unroll
            for (int off = 16; off; off >>= 1)
                M[n] += __shfl_xor_sync(0xffffffffu, M[n], off);
        }
        if (lane == 0) {
            #pragma unroll
            for (int n = 0; n < NMOM; n++) mom[half][wl][n] = M[n];
        }
    }

    // ---- reflections: direct, contiguous per-warp slices ----
    {
        float A0 = 0.f, A1 = 0.f;
        int l0 = (bL * wl) >> 2, l1 = (bL * (wl + 1)) >> 2;
        for (int j = l0; j < l1; j++) {
            float s = x + u[j];
            A1 += ex2(K2C * s * s);
        }
        const int rlen = B_ROWS - aR;
        const float xc = x - c2;
        int r0 = aR + ((rlen * wl) >> 2), r1 = aR + ((rlen * (wl + 1)) >> 2);
        for (int j = r0; j < r1; j++) {
            float s = xc + u[j];
            A0 += ex2(K2C * s * s);
        }
        refl[half][lane][wl] = A0 + A1;
    }
    __syncthreads();

    if (wl == 0) {
        float Mn[NMOM];
        #pragma unroll
        for (int n = 0; n < NMOM; n++)
            Mn[n] = (mom[half][0][n] + mom[half][1][n])
                  + (mom[half][2][n] + mom[half][3][n]);
        const float delta = x - cen;
        float f = Mn[NMOM - 1];
        #pragma unroll
        for (int n = NMOM - 2; n >= 0; n--)
            f = fmaf(f, delta, Mn[n]);
        f += (refl[half][lane][0] + refl[half][lane][1])
           + (refl[half][lane][2] + refl[half][lane][3]);

        const float Bf = (float)B_ROWS;
        const float scale = ih * (1.0f / (Bf * 2.5066282746310002f));
        float l = logf(f * scale + 1e-8f);
        #pragma unroll
        for (int off = 16; off; off >>= 1)
            l += __shfl_xor_sync(0xffffffffu, l, off);
        if (lane == 0)
            g_partials[col * QCH + chunk] = l;
    }
    __syncthreads();

    if (tid == 0) {
        __threadfence();
        unsigned p = atomicAdd(&g_done, 1);
        sdone = (p == NBLK_K2 - 1);
    }
    __syncthreads();
    if (!sdone) return;
    __threadfence();

    if (tid < N_DIM) {
        float t = 0.f;
        #pragma unroll
        for (int c = 0; c < QCH; c++)
            t += g_partials[tid * QCH + c];
        out[1 + tid] = -t / (float)B_ROWS;
    }
    double s = 0.0;
    for (int i = tid; i < B_ROWS; i += 256) s += (double)g_logrho[i];
    dred[tid] = s; __syncthreads();
    for (int st = 128; st > 0; st >>= 1) {
        if (tid < st) dred[tid] += dred[tid + st];
        __syncthreads();
    }
    if (tid == 0) {
        const int k = *kp;
        const double EULER    = 0.5772156649015328606;
        const double DG_B     = 6.9309834448765934;     // psi(1024)
        const double LGAMMA33 = 81.55795945611503558;   // lgamma(64/2+1)
        const double LOG_PI   = 1.1447298858494001741;
        const double INV_LN2  = 1.4426950408889634074;
        double dg_k = -EULER;
        for (int i = 1; i < k; i++) dg_k += 1.0 / (double)i;
        double log_c_d = 0.5 * (double)N_DIM * LOG_PI - LGAMMA33;
        double mean_lr = dred[0] / (double)B_ROWS;
        double h_nats = -dg_k + DG_B + log_c_d + (double)N_DIM * 0.5 * mean_lr;
        out[0] = (float)(h_nats * INV_LN2);
    }
}

// ---------------------------------------------------------------------------
extern "C" void kernel_launch(void* const* d_in, const int* in_sizes, int n_in,
                              void* d_out, int out_size) {
    const float* act = (const float*)d_in[0];
    const int*   kp  = (const int*)d_in[1];
    float* out = (float*)d_out;
    (void)in_sizes; (void)n_in; (void)out_size;

    k1<<<NBLK_KNN + N_DIM, 256>>>(act, kp);
    dim3 g(N_DIM, 16);
    k2<<<g, 256>>>(kp, out);
}